// round 5
// baseline (speedup 1.0000x reference)
#include <cuda_runtime.h>
#include <cstdint>
#include <math.h>

#define N_  128
#define T_  1000
#define DO_ 256
#define DS_ 64
#define DU_ 8
#define HE_ 512
#define HG_ 128
#define HD_ 256
#define DN_ 128
#define NT_ (N_*T_)

typedef unsigned long long u64;

// ---------------- f32x2 packed math helpers ----------------
__device__ __forceinline__ u64 pk2(float lo, float hi) {
    u64 r; asm("mov.b64 %0, {%1, %2};" : "=l"(r) : "f"(lo), "f"(hi)); return r;
}
__device__ __forceinline__ u64 dup2(float x) {
    u64 r; asm("mov.b64 %0, {%1, %1};" : "=l"(r) : "f"(x)); return r;
}
__device__ __forceinline__ u64 fma2(u64 a, u64 b, u64 c) {
    u64 d; asm("fma.rn.f32x2 %0, %1, %2, %3;" : "=l"(d) : "l"(a), "l"(b), "l"(c)); return d;
}
__device__ __forceinline__ float2 upk(u64 v) {
    float2 f; asm("mov.b64 {%0, %1}, %2;" : "=f"(f.x), "=f"(f.y) : "l"(v)); return f;
}

// ---------------- cp.async helpers ----------------
__device__ __forceinline__ void cp_async16(uint32_t saddr, const void* gptr) {
    asm volatile("cp.async.cg.shared.global [%0], [%1], 16;" :: "r"(saddr), "l"(gptr));
}
__device__ __forceinline__ void cp_commit() { asm volatile("cp.async.commit_group;"); }
__device__ __forceinline__ void cp_wait0()  { asm volatile("cp.async.wait_group 0;"); }

// ---------------- scratch ----------------
__device__ float g_h[(size_t)NT_ * HE_];
__device__ float g_a[(size_t)NT_ * DN_];
__device__ float g_gall[(size_t)NT_ * 3 * HG_];
__device__ float g_hs[(size_t)NT_ * HG_];
__device__ float g_ab[(size_t)NT_ * DN_];
__device__ float g_maskA[NT_];
__device__ float g_maskB[NT_];
__device__ float g_maskAB[NT_];
__device__ unsigned int g_skeys[(size_t)NT_ * 2];
__device__ unsigned int g_keys[8];
__device__ float g_p;

// ---------------- Threefry2x32 (JAX-compatible) ----------------
__device__ __forceinline__ void tf_round(unsigned int& x0, unsigned int& x1, int r) {
    x0 += x1;
    x1 = __funnelshift_l(x1, x1, r);
    x1 ^= x0;
}

__device__ __forceinline__ uint2 tf2x32(unsigned int k0, unsigned int k1,
                                        unsigned int c0, unsigned int c1) {
    unsigned int ks2 = k0 ^ k1 ^ 0x1BD11BDAu;
    unsigned int x0 = c0 + k0;
    unsigned int x1 = c1 + k1;
    tf_round(x0,x1,13); tf_round(x0,x1,15); tf_round(x0,x1,26); tf_round(x0,x1,6);
    x0 += k1;  x1 += ks2 + 1u;
    tf_round(x0,x1,17); tf_round(x0,x1,29); tf_round(x0,x1,16); tf_round(x0,x1,24);
    x0 += ks2; x1 += k0 + 2u;
    tf_round(x0,x1,13); tf_round(x0,x1,15); tf_round(x0,x1,26); tf_round(x0,x1,6);
    x0 += k0;  x1 += k1 + 3u;
    tf_round(x0,x1,17); tf_round(x0,x1,29); tf_round(x0,x1,16); tf_round(x0,x1,24);
    x0 += k1;  x1 += ks2 + 4u;
    tf_round(x0,x1,13); tf_round(x0,x1,15); tf_round(x0,x1,26); tf_round(x0,x1,6);
    x0 += ks2; x1 += k0 + 5u;
    return make_uint2(x0, x1);
}

__device__ __forceinline__ float bits_to_unit(unsigned int bits) {
    return __uint_as_float((bits >> 9) | 0x3f800000u) - 1.0f;
}

__device__ __forceinline__ float softplusf(float x) {
    return fmaxf(x, 0.0f) + log1pf(expf(-fabsf(x)));
}

// ---------------- key derivation ----------------
__global__ void key_kernel(const int* seed, const float* dropout) {
    if (threadIdx.x == 0 && blockIdx.x == 0) {
        unsigned int k0 = 0u, k1 = (unsigned int)seed[0];
        uint2 keyF = tf2x32(k0, k1, 0u, 0u);
        uint2 enc  = tf2x32(k0, k1, 0u, 1u);
        uint2 kA = tf2x32(enc.x, enc.y, 0u, 0u);
        uint2 s1 = tf2x32(enc.x, enc.y, 0u, 1u);
        uint2 kB = tf2x32(s1.x, s1.y, 0u, 0u);
        uint2 s2 = tf2x32(s1.x, s1.y, 0u, 1u);
        uint2 kAB = tf2x32(s2.x, s2.y, 0u, 0u);
        g_keys[0] = kA.x;  g_keys[1] = kA.y;
        g_keys[2] = kB.x;  g_keys[3] = kB.y;
        g_keys[4] = kAB.x; g_keys[5] = kAB.y;
        g_keys[6] = keyF.x; g_keys[7] = keyF.y;
        g_p = 1.0f - dropout[0];
    }
}

// ---------------- bernoulli masks ----------------
__global__ void mask_kernel() {
    int idx = blockIdx.x * blockDim.x + threadIdx.x;
    if (idx >= NT_) return;
    float p = g_p;
    unsigned int ci = (unsigned int)idx;
    uint2 ra = tf2x32(g_keys[0], g_keys[1], 0u, ci);
    uint2 rb = tf2x32(g_keys[2], g_keys[3], 0u, ci);
    uint2 rc = tf2x32(g_keys[4], g_keys[5], 0u, ci);
    g_maskA[idx]  = (bits_to_unit(ra.x ^ ra.y) < p) ? 1.0f : 0.0f;
    g_maskB[idx]  = (bits_to_unit(rb.x ^ rb.y) < p) ? 1.0f : 0.0f;
    g_maskAB[idx] = (bits_to_unit(rc.x ^ rc.y) < p) ? 1.0f : 0.0f;
}

// ---------------- serial per-sequence key chain (side stream) ----------------
__global__ void chain_kernel() {
    int n = blockIdx.x * blockDim.x + threadIdx.x;
    if (n >= N_) return;
    uint2 kk = tf2x32(g_keys[6], g_keys[7], 0u, (unsigned int)n);
    for (int t = 0; t < T_; t++) {
        uint2 sk = tf2x32(kk.x, kk.y, 0u, 1u);
        uint2 nk = tf2x32(kk.x, kk.y, 0u, 0u);
        size_t row = (size_t)n * T_ + t;
        g_skeys[row * 2 + 0] = sk.x;
        g_skeys[row * 2 + 1] = sk.y;
        kk = nk;
    }
}

// ---------------- 128x128x32 SGEMM: k-major A (no dup), cp.async B, f32x2 ----------------
#define KT_       32
#define S_STRIDE  132
#define S_TILE    (KT_ * S_STRIDE)          // 4224 floats per stage
#define SMEM_FLOATS (4 * S_TILE)            // As x2 stages + Bs x2 stages

template <int EPI>
__global__ void __launch_bounds__(256, 2) sgemm_k(
    const float* __restrict__ A, const float* __restrict__ B,
    const float* __restrict__ bias, float* __restrict__ C,
    int M, int Nn, int K,
    const float* __restrict__ mask1, const float* __restrict__ mask2,
    const float* __restrict__ aux)
{
    extern __shared__ __align__(16) float sm[];
    float* AsBase = sm;                 // 2 * S_TILE  (As[k][m], k-major)
    float* BsBase = sm + 2 * S_TILE;    // 2 * S_TILE  (Bs[k][n], k-major)

    const int bm = blockIdx.y * 128;
    const int bn = blockIdx.x * 128;
    const int tid = threadIdx.x;

    const int ty = tid >> 4;            // 0..15
    const int tx = tid & 15;            // 0..15

    // A load mapping: thread -> (m = tid>>1, kHalf = (tid&1)*16), 4 float4 along k
    const int am = tid >> 1;
    const int akh = (tid & 1) * 16;
    // B cp.async mapping: thread -> (kRow = tid>>3), 4 chunks of 16B along n
    const int bkr = tid >> 3;
    const int bc0 = (tid & 7) * 4;

    u64 acc[8][4];
#pragma unroll
    for (int i = 0; i < 8; i++)
#pragma unroll
        for (int j = 0; j < 4; j++) acc[i][j] = 0ULL;

    const float* Ap = A + (size_t)(bm + am) * K + akh;
    const float* Bp = B + (size_t)bkr * Nn + bn;

    uint32_t bs_sm = (uint32_t)__cvta_generic_to_shared(BsBase + (size_t)bkr * S_STRIDE + bc0);
    const uint32_t stage_b = (uint32_t)(S_TILE * sizeof(float));

    const int ntiles = K / KT_;

    // ---- prologue: tile 0 ----
    {
#pragma unroll
        for (int c = 0; c < 4; c++)
            cp_async16(bs_sm + (uint32_t)(c * 32 * sizeof(float)), Bp + bc0 + c * 32);
        cp_commit();
        float4 av[4];
#pragma unroll
        for (int c = 0; c < 4; c++) av[c] = *(const float4*)(Ap + c * 4);
        float* as0 = AsBase;
#pragma unroll
        for (int c = 0; c < 4; c++) {
            as0[(akh + c * 4 + 0) * S_STRIDE + am] = av[c].x;
            as0[(akh + c * 4 + 1) * S_STRIDE + am] = av[c].y;
            as0[(akh + c * 4 + 2) * S_STRIDE + am] = av[c].z;
            as0[(akh + c * 4 + 3) * S_STRIDE + am] = av[c].w;
        }
        cp_wait0();
    }
    __syncthreads();

    for (int kt = 0; kt < ntiles; kt++) {
        const int cur = kt & 1;
        const int nxt = cur ^ 1;
        const bool more = (kt + 1) < ntiles;
        float4 av[4];
        if (more) {
            const float* bsrc = Bp + (size_t)(kt + 1) * KT_ * Nn;
#pragma unroll
            for (int c = 0; c < 4; c++)
                cp_async16(bs_sm + (uint32_t)nxt * stage_b + (uint32_t)(c * 32 * sizeof(float)),
                           bsrc + bc0 + c * 32);
            cp_commit();
            const float* asrc = Ap + (kt + 1) * KT_;
#pragma unroll
            for (int c = 0; c < 4; c++) av[c] = *(const float4*)(asrc + c * 4);
        }

        const float* Asc = AsBase + (size_t)cur * S_TILE;
        const float* Bsc = BsBase + (size_t)cur * S_TILE;
#pragma unroll
        for (int k = 0; k < KT_; k++) {
            const float* as = Asc + (size_t)k * S_STRIDE + ty * 8;
            float4 af0 = *(const float4*)(as);
            float4 af1 = *(const float4*)(as + 4);
            const float* bs = Bsc + (size_t)k * S_STRIDE + tx * 8;
            ulonglong2 bv0 = *(const ulonglong2*)(bs);
            ulonglong2 bv1 = *(const ulonglong2*)(bs + 4);
            u64 bb[4] = {bv0.x, bv0.y, bv1.x, bv1.y};
            u64 aa[8] = {dup2(af0.x), dup2(af0.y), dup2(af0.z), dup2(af0.w),
                         dup2(af1.x), dup2(af1.y), dup2(af1.z), dup2(af1.w)};
#pragma unroll
            for (int i = 0; i < 8; i++)
#pragma unroll
                for (int j = 0; j < 4; j++)
                    acc[i][j] = fma2(aa[i], bb[j], acc[i][j]);
        }

        if (more) {
            float* asn = AsBase + (size_t)nxt * S_TILE;
#pragma unroll
            for (int c = 0; c < 4; c++) {
                asn[(akh + c * 4 + 0) * S_STRIDE + am] = av[c].x;
                asn[(akh + c * 4 + 1) * S_STRIDE + am] = av[c].y;
                asn[(akh + c * 4 + 2) * S_STRIDE + am] = av[c].z;
                asn[(akh + c * 4 + 3) * S_STRIDE + am] = av[c].w;
            }
            cp_wait0();
        }
        __syncthreads();
    }

    // ---- epilogue ----
#pragma unroll
    for (int i = 0; i < 8; i++) {
        const int row = bm + ty * 8 + i;
        float m1 = 0.0f, m2 = 0.0f;
        if (EPI == 1) m1 = mask1[row];
        if (EPI == 3) { m1 = mask1[row]; m2 = mask2[row]; }
        float vals[8];
#pragma unroll
        for (int j = 0; j < 4; j++) {
            float2 f = upk(acc[i][j]);
            vals[2 * j]     = f.x;
            vals[2 * j + 1] = f.y;
        }
        float out8[8];
#pragma unroll
        for (int jj = 0; jj < 8; jj++) {
            const int col = bn + tx * 8 + jj;
            float c = vals[jj] + bias[col];
            if (EPI == 0) {
                c = tanhf(c);
            } else if (EPI == 1) {
                if (col >= 64) c = -softplusf(c);
                c *= m1;
            } else if (EPI == 3) {
                if (col >= 64) c = -softplusf(c);
                c *= m1;
                c = m2 * (aux[(size_t)row * 128 + col] + c);
            }
            out8[jj] = c;
        }
        float4* cp = (float4*)(C + (size_t)row * Nn + bn + tx * 8);
        cp[0] = make_float4(out8[0], out8[1], out8[2], out8[3]);
        cp[1] = make_float4(out8[4], out8[5], out8[6], out8[7]);
    }
}

// ---------------- GRU: 2 syncs/step, Ug column-resident, f32x2 dots ----------------
__global__ void __launch_bounds__(384, 1) gru_kernel(const float* __restrict__ Ug) {
    const int n = blockIdx.x;
    const int j = threadIdx.x;  // 0..383
    __shared__ __align__(16) float h[128];
    __shared__ float rbuf[128], zbuf[128];
    u64 ug2[64];
#pragma unroll
    for (int k2 = 0; k2 < 64; k2++)
        ug2[k2] = pk2(Ug[(2 * k2) * 384 + j], Ug[(2 * k2 + 1) * 384 + j]);
    if (j < 128) h[j] = 0.0f;

    const float* gbase = g_gall + (size_t)n * T_ * 384;
    float gv = gbase[j];
    __syncthreads();
    for (int t = 0; t < T_; t++) {
        float gvn = 0.0f;
        if (t + 1 < T_) gvn = gbase[(size_t)(t + 1) * 384 + j];

        u64 s4[4] = {0ULL, 0ULL, 0ULL, 0ULL};
#pragma unroll
        for (int k = 0; k < 128; k += 8) {
            ulonglong2 h0 = *(const ulonglong2*)&h[k];
            ulonglong2 h1 = *(const ulonglong2*)&h[k + 4];
            s4[0] = fma2(h0.x, ug2[k / 2],     s4[0]);
            s4[1] = fma2(h0.y, ug2[k / 2 + 1], s4[1]);
            s4[2] = fma2(h1.x, ug2[k / 2 + 2], s4[2]);
            s4[3] = fma2(h1.y, ug2[k / 2 + 3], s4[3]);
        }
        float2 f0 = upk(s4[0]), f1 = upk(s4[1]), f2 = upk(s4[2]), f3 = upk(s4[3]);
        float s = ((f0.x + f0.y) + (f1.x + f1.y)) + ((f2.x + f2.y) + (f3.x + f3.y));
        if (j < 256) {
            float val = 1.0f / (1.0f + expf(-(gv + s)));
            if (j < 128) rbuf[j] = val; else zbuf[j - 128] = val;
        }
        __syncthreads();
        if (j >= 256) {
            const int jj = j - 256;
            float nn = tanhf(gv + rbuf[jj] * s);
            float z  = zbuf[jj];
            float hn = (1.0f - z) * nn + z * h[jj];
            h[jj] = hn;
            g_hs[(size_t)(n * T_ + t) * 128 + jj] = hn;
        }
        gv = gvn;
        __syncthreads();
    }
}

// ---------------- filter: 256 compute + 64 RNG threads; noise off critical path ----------------
__global__ void __launch_bounds__(320, 1) filter_kernel(
    const float* __restrict__ u, const float* __restrict__ Wd1,
    const float* __restrict__ bd1, const float* __restrict__ Wd2,
    const float* __restrict__ bd2, const float* __restrict__ logQ,
    float* __restrict__ out)
{
    const int n = blockIdx.x;
    const int tid = threadIdx.x;          // 0..319
    const bool isC = tid < 256;
    const int q = tid >> 6, j = tid & 63;
    const int r = tid - 256;              // rng lane 0..63 (when !isC)
    __shared__ __align__(16) float xbuf[72];
    __shared__ __align__(16) float hdyn[256];
    __shared__ float part[4][64];
    __shared__ float noi[2][64];

    u64 wc2[36];
    u64 w2[32];
    float bd1v = 0.0f, bd2j = 0.0f, Qj = 0.0f;
    if (isC) {
#pragma unroll
        for (int m = 0; m < 36; m++)
            wc2[m] = pk2(Wd1[(2 * m) * 256 + tid], Wd1[(2 * m + 1) * 256 + tid]);
#pragma unroll
        for (int m = 0; m < 32; m++)
            w2[m] = pk2(Wd2[(q * 64 + 2 * m) * 64 + j], Wd2[(q * 64 + 2 * m + 1) * 64 + j]);
        bd1v = bd1[tid];
        if (tid < 64) { bd2j = bd2[j]; Qj = softplusf(logQ[j]); }
    }

    float* outZ = out;
    float* outS = out + (size_t)NT_ * 64;
    float* outP = out + (size_t)NT_ * 192;

    const size_t base = (size_t)n * T_;
    float vcur = 1.0f;
    float a1c = 0.0f, a2c = 0.0f, uc = 0.0f;
    unsigned int s0n = 0u, s1n = 0u;

    if (isC) {
        if (tid < 64) {
            xbuf[tid] = 0.0f;
            a1c = g_ab[base * 128 + j];
            a2c = g_ab[base * 128 + 64 + j];
        } else if (tid < 72) {
            xbuf[tid] = u[base * 8 + (tid - 64)];
            uc = (T_ > 1) ? u[(base + 1) * 8 + (tid - 64)] : 0.0f;
        }
    } else {
        // noise for t=0
        unsigned int s0 = g_skeys[base * 2], s1 = g_skeys[base * 2 + 1];
        uint2 rr = tf2x32(s0, s1, 0u, (unsigned int)r);
        float f = bits_to_unit(rr.x ^ rr.y);
        float uu = __fadd_rn(__fmul_rn(f, 2.0f), -0.99999994f);
        uu = fmaxf(uu, -0.99999994f);
        noi[0][r] = 1.41421356f * erfinvf(uu);
        if (T_ > 1) { s0n = g_skeys[(base + 1) * 2]; s1n = g_skeys[(base + 1) * 2 + 1]; }
    }
    __syncthreads();

    for (int t = 0; t < T_; t++) {
        const size_t row = base + t;
        float a1n = 0.0f, a2n = 0.0f, un = 0.0f;

        if (isC) {
            // prefetch next-step inputs (hide under dots)
            if (t + 1 < T_) {
                if (tid < 64) {
                    a1n = g_ab[(row + 1) * 128 + j];
                    a2n = g_ab[(row + 1) * 128 + 64 + j];
                } else if (tid < 72 && t + 2 < T_) {
                    un = u[(row + 2) * 8 + (tid - 64)];
                }
            }
            // hdyn = tanh([m,u] @ Wd1 + bd1)
            u64 s2a = pk2(bd1v, 0.0f), s2b = 0ULL;
#pragma unroll
            for (int k = 0; k < 72; k += 4) {
                ulonglong2 xv = *(const ulonglong2*)&xbuf[k];
                s2a = fma2(xv.x, wc2[k / 2],     s2a);
                s2b = fma2(xv.y, wc2[k / 2 + 1], s2b);
            }
            float2 fa = upk(s2a), fb = upk(s2b);
            hdyn[tid] = tanhf((fa.x + fa.y) + (fb.x + fb.y));
        } else {
            // RNG warps: noise for step t+1
            if (t + 1 < T_) {
                uint2 rr = tf2x32(s0n, s1n, 0u, (unsigned int)r);
                float f = bits_to_unit(rr.x ^ rr.y);
                float uu = __fadd_rn(__fmul_rn(f, 2.0f), -0.99999994f);
                uu = fmaxf(uu, -0.99999994f);
                noi[(t + 1) & 1][r] = 1.41421356f * erfinvf(uu);
                if (t + 2 < T_) {
                    s0n = g_skeys[(row + 2) * 2];
                    s1n = g_skeys[(row + 2) * 2 + 1];
                }
            }
        }
        __syncthreads();

        if (isC) {
            // m_p partial: hdyn @ Wd2
            u64 p2a = 0ULL, p2b = 0ULL;
#pragma unroll
            for (int k = 0; k < 64; k += 4) {
                ulonglong2 hv = *(const ulonglong2*)&hdyn[q * 64 + k];
                p2a = fma2(hv.x, w2[k / 2],     p2a);
                p2b = fma2(hv.y, w2[k / 2 + 1], p2b);
            }
            float2 fa = upk(p2a), fb = upk(p2b);
            part[q][j] = (fa.x + fa.y) + (fb.x + fb.y);
        }
        __syncthreads();

        if (tid < 64) {
            float mp = ((part[0][j] + part[1][j]) + (part[2][j] + part[3][j])) + bd2j;
            float vp = vcur + Qj;
            float Jp = 1.0f / vp;
            float hp = mp * Jp;
            float Jpost = Jp - 2.0f * a2c;
            float vn = 1.0f / Jpost;
            float mn = (hp + a1c) * vn;
            float zz = mn + sqrtf(vn) * noi[t & 1][j];
            xbuf[j] = mn;
            vcur = vn;
            outZ[row * 64 + j] = zz;
            outS[row * 128 + j] = mn;
            outS[row * 128 + 64 + j] = vn;
            outP[row * 128 + j] = mp;
            outP[row * 128 + 64 + j] = vp;
            a1c = a1n; a2c = a2n;
        } else if (tid < 72) {
            xbuf[tid] = uc;   // u for step t+1
            uc = un;
        }
        __syncthreads();
    }
}

// ---------------- host launcher ----------------
extern "C" void kernel_launch(void* const* d_in, const int* in_sizes, int n_in,
                              void* d_out, int out_size) {
    (void)in_sizes; (void)n_in; (void)out_size;
    const int*   seed    = (const int*)d_in[3];
    const float* dropout = (const float*)d_in[4];
    const float* y   = (const float*)d_in[1];
    const float* u   = (const float*)d_in[2];
    const float* W1  = (const float*)d_in[5];
    const float* b1  = (const float*)d_in[6];
    const float* W2  = (const float*)d_in[7];
    const float* b2  = (const float*)d_in[8];
    const float* Wg  = (const float*)d_in[9];
    const float* Ug  = (const float*)d_in[10];
    const float* bg  = (const float*)d_in[11];
    const float* Wo  = (const float*)d_in[12];
    const float* bo  = (const float*)d_in[13];
    const float* Wd1 = (const float*)d_in[14];
    const float* bd1 = (const float*)d_in[15];
    const float* Wd2 = (const float*)d_in[16];
    const float* bd2 = (const float*)d_in[17];
    const float* logQ= (const float*)d_in[18];
    float* out = (float*)d_out;

    float *ph, *pa, *pg, *phs, *pab, *pmA, *pmB, *pmAB;
    cudaGetSymbolAddress((void**)&ph,   g_h);
    cudaGetSymbolAddress((void**)&pa,   g_a);
    cudaGetSymbolAddress((void**)&pg,   g_gall);
    cudaGetSymbolAddress((void**)&phs,  g_hs);
    cudaGetSymbolAddress((void**)&pab,  g_ab);
    cudaGetSymbolAddress((void**)&pmA,  g_maskA);
    cudaGetSymbolAddress((void**)&pmB,  g_maskB);
    cudaGetSymbolAddress((void**)&pmAB, g_maskAB);

    const int smem_bytes = SMEM_FLOATS * (int)sizeof(float);

    static cudaStream_t s_chain = nullptr;
    static cudaEvent_t ev_fork = nullptr, ev_join = nullptr;
    if (s_chain == nullptr) {
        cudaStreamCreateWithFlags(&s_chain, cudaStreamNonBlocking);
        cudaEventCreateWithFlags(&ev_fork, cudaEventDisableTiming);
        cudaEventCreateWithFlags(&ev_join, cudaEventDisableTiming);
        cudaFuncSetAttribute(sgemm_k<0>, cudaFuncAttributeMaxDynamicSharedMemorySize, smem_bytes);
        cudaFuncSetAttribute(sgemm_k<1>, cudaFuncAttributeMaxDynamicSharedMemorySize, smem_bytes);
        cudaFuncSetAttribute(sgemm_k<2>, cudaFuncAttributeMaxDynamicSharedMemorySize, smem_bytes);
        cudaFuncSetAttribute(sgemm_k<3>, cudaFuncAttributeMaxDynamicSharedMemorySize, smem_bytes);
    }

    key_kernel<<<1, 1>>>(seed, dropout);

    // fork: serial Threefry chain overlaps the GEMM pipeline
    cudaEventRecord(ev_fork, 0);
    cudaStreamWaitEvent(s_chain, ev_fork, 0);
    chain_kernel<<<1, 128, 0, s_chain>>>();
    cudaEventRecord(ev_join, s_chain);

    mask_kernel<<<(NT_ + 255) / 256, 256>>>();

    // h = tanh(y @ W1 + b1)
    sgemm_k<0><<<dim3(HE_ / 128, NT_ / 128), 256, smem_bytes>>>(y, W1, b1, ph, NT_, HE_, DO_,
                                                                nullptr, nullptr, nullptr);
    // a = constrain(h @ W2 + b2) * maskA
    sgemm_k<1><<<dim3(DN_ / 128, NT_ / 128), 256, smem_bytes>>>(ph, W2, b2, pa, NT_, DN_, HE_,
                                                                pmA, nullptr, nullptr);
    // g_all = a @ Wg + bg
    sgemm_k<2><<<dim3(3 * HG_ / 128, NT_ / 128), 256, smem_bytes>>>(pa, Wg, bg, pg, NT_, 3 * HG_, DN_,
                                                                    nullptr, nullptr, nullptr);
    // GRU scan
    gru_kernel<<<N_, 384>>>(Ug);
    // ab = maskAB * (a + constrain(hs @ Wo + bo) * maskB)
    sgemm_k<3><<<dim3(DN_ / 128, NT_ / 128), 256, smem_bytes>>>(phs, Wo, bo, pab, NT_, DN_, HG_,
                                                                pmB, pmAB, pa);

    // join: filter needs the sample subkeys
    cudaStreamWaitEvent(0, ev_join, 0);
    // filter + sampling
    filter_kernel<<<N_, 320>>>(u, Wd1, bd1, Wd2, bd2, logQ, out);
}

// round 6
// speedup vs baseline: 1.1548x; 1.1548x over previous
#include <cuda_runtime.h>
#include <cstdint>
#include <math.h>

#define N_  128
#define T_  1000
#define DO_ 256
#define DS_ 64
#define DU_ 8
#define HE_ 512
#define HG_ 128
#define HD_ 256
#define DN_ 128
#define NT_ (N_*T_)

typedef unsigned long long u64;

// ---------------- f32x2 packed math helpers ----------------
__device__ __forceinline__ u64 pk2(float lo, float hi) {
    u64 r; asm("mov.b64 %0, {%1, %2};" : "=l"(r) : "f"(lo), "f"(hi)); return r;
}
__device__ __forceinline__ u64 dup2(float x) {
    u64 r; asm("mov.b64 %0, {%1, %1};" : "=l"(r) : "f"(x)); return r;
}
__device__ __forceinline__ u64 fma2(u64 a, u64 b, u64 c) {
    u64 d; asm("fma.rn.f32x2 %0, %1, %2, %3;" : "=l"(d) : "l"(a), "l"(b), "l"(c)); return d;
}
__device__ __forceinline__ float2 upk(u64 v) {
    float2 f; asm("mov.b64 {%0, %1}, %2;" : "=f"(f.x), "=f"(f.y) : "l"(v)); return f;
}

// ---------------- cp.async helpers ----------------
__device__ __forceinline__ void cp_async16(uint32_t saddr, const void* gptr) {
    asm volatile("cp.async.cg.shared.global [%0], [%1], 16;" :: "r"(saddr), "l"(gptr));
}
__device__ __forceinline__ void cp_commit() { asm volatile("cp.async.commit_group;"); }
__device__ __forceinline__ void cp_wait0()  { asm volatile("cp.async.wait_group 0;"); }

// ---------------- scratch ----------------
__device__ float g_h[(size_t)NT_ * HE_];
__device__ float g_a[(size_t)NT_ * DN_];
__device__ float g_gall[(size_t)NT_ * 3 * HG_];
__device__ float g_hs[(size_t)NT_ * HG_];
__device__ float g_ab[(size_t)NT_ * DN_];
__device__ float g_maskA[NT_];
__device__ float g_maskB[NT_];
__device__ float g_maskAB[NT_];
__device__ unsigned int g_skeys[(size_t)NT_ * 2];
__device__ unsigned int g_keys[8];
__device__ float g_p;

// ---------------- Threefry2x32 (JAX-compatible) ----------------
__device__ __forceinline__ void tf_round(unsigned int& x0, unsigned int& x1, int r) {
    x0 += x1;
    x1 = __funnelshift_l(x1, x1, r);
    x1 ^= x0;
}

__device__ __forceinline__ uint2 tf2x32(unsigned int k0, unsigned int k1,
                                        unsigned int c0, unsigned int c1) {
    unsigned int ks2 = k0 ^ k1 ^ 0x1BD11BDAu;
    unsigned int x0 = c0 + k0;
    unsigned int x1 = c1 + k1;
    tf_round(x0,x1,13); tf_round(x0,x1,15); tf_round(x0,x1,26); tf_round(x0,x1,6);
    x0 += k1;  x1 += ks2 + 1u;
    tf_round(x0,x1,17); tf_round(x0,x1,29); tf_round(x0,x1,16); tf_round(x0,x1,24);
    x0 += ks2; x1 += k0 + 2u;
    tf_round(x0,x1,13); tf_round(x0,x1,15); tf_round(x0,x1,26); tf_round(x0,x1,6);
    x0 += k0;  x1 += k1 + 3u;
    tf_round(x0,x1,17); tf_round(x0,x1,29); tf_round(x0,x1,16); tf_round(x0,x1,24);
    x0 += k1;  x1 += ks2 + 4u;
    tf_round(x0,x1,13); tf_round(x0,x1,15); tf_round(x0,x1,26); tf_round(x0,x1,6);
    x0 += ks2; x1 += k0 + 5u;
    return make_uint2(x0, x1);
}

__device__ __forceinline__ float bits_to_unit(unsigned int bits) {
    return __uint_as_float((bits >> 9) | 0x3f800000u) - 1.0f;
}

__device__ __forceinline__ float softplusf(float x) {
    return fmaxf(x, 0.0f) + log1pf(expf(-fabsf(x)));
}

// ---------------- key derivation ----------------
__global__ void key_kernel(const int* seed, const float* dropout) {
    if (threadIdx.x == 0 && blockIdx.x == 0) {
        unsigned int k0 = 0u, k1 = (unsigned int)seed[0];
        uint2 keyF = tf2x32(k0, k1, 0u, 0u);
        uint2 enc  = tf2x32(k0, k1, 0u, 1u);
        uint2 kA = tf2x32(enc.x, enc.y, 0u, 0u);
        uint2 s1 = tf2x32(enc.x, enc.y, 0u, 1u);
        uint2 kB = tf2x32(s1.x, s1.y, 0u, 0u);
        uint2 s2 = tf2x32(s1.x, s1.y, 0u, 1u);
        uint2 kAB = tf2x32(s2.x, s2.y, 0u, 0u);
        g_keys[0] = kA.x;  g_keys[1] = kA.y;
        g_keys[2] = kB.x;  g_keys[3] = kB.y;
        g_keys[4] = kAB.x; g_keys[5] = kAB.y;
        g_keys[6] = keyF.x; g_keys[7] = keyF.y;
        g_p = 1.0f - dropout[0];
    }
}

// ---------------- bernoulli masks ----------------
__global__ void mask_kernel() {
    int idx = blockIdx.x * blockDim.x + threadIdx.x;
    if (idx >= NT_) return;
    float p = g_p;
    unsigned int ci = (unsigned int)idx;
    uint2 ra = tf2x32(g_keys[0], g_keys[1], 0u, ci);
    uint2 rb = tf2x32(g_keys[2], g_keys[3], 0u, ci);
    uint2 rc = tf2x32(g_keys[4], g_keys[5], 0u, ci);
    g_maskA[idx]  = (bits_to_unit(ra.x ^ ra.y) < p) ? 1.0f : 0.0f;
    g_maskB[idx]  = (bits_to_unit(rb.x ^ rb.y) < p) ? 1.0f : 0.0f;
    g_maskAB[idx] = (bits_to_unit(rc.x ^ rc.y) < p) ? 1.0f : 0.0f;
}

// ---------------- serial per-sequence key chain (side stream) ----------------
__global__ void chain_kernel() {
    int n = blockIdx.x * blockDim.x + threadIdx.x;
    if (n >= N_) return;
    uint2 kk = tf2x32(g_keys[6], g_keys[7], 0u, (unsigned int)n);
    for (int t = 0; t < T_; t++) {
        uint2 sk = tf2x32(kk.x, kk.y, 0u, 1u);
        uint2 nk = tf2x32(kk.x, kk.y, 0u, 0u);
        size_t row = (size_t)n * T_ + t;
        g_skeys[row * 2 + 0] = sk.x;
        g_skeys[row * 2 + 1] = sk.y;
        kk = nk;
    }
}

// ---------------- 128x128x32 SGEMM: k-major A, cp.async B, f32x2 (R5 form) ----------------
#define KT_       32
#define S_STRIDE  132
#define S_TILE    (KT_ * S_STRIDE)
#define SMEM_FLOATS (4 * S_TILE)

template <int EPI>
__global__ void __launch_bounds__(256, 2) sgemm_k(
    const float* __restrict__ A, const float* __restrict__ B,
    const float* __restrict__ bias, float* __restrict__ C,
    int M, int Nn, int K,
    const float* __restrict__ mask1, const float* __restrict__ mask2,
    const float* __restrict__ aux)
{
    extern __shared__ __align__(16) float sm[];
    float* AsBase = sm;
    float* BsBase = sm + 2 * S_TILE;

    const int bm = blockIdx.y * 128;
    const int bn = blockIdx.x * 128;
    const int tid = threadIdx.x;

    const int ty = tid >> 4;
    const int tx = tid & 15;

    const int am = tid >> 1;
    const int akh = (tid & 1) * 16;
    const int bkr = tid >> 3;
    const int bc0 = (tid & 7) * 4;

    u64 acc[8][4];
#pragma unroll
    for (int i = 0; i < 8; i++)
#pragma unroll
        for (int j = 0; j < 4; j++) acc[i][j] = 0ULL;

    const float* Ap = A + (size_t)(bm + am) * K + akh;
    const float* Bp = B + (size_t)bkr * Nn + bn;

    uint32_t bs_sm = (uint32_t)__cvta_generic_to_shared(BsBase + (size_t)bkr * S_STRIDE + bc0);
    const uint32_t stage_b = (uint32_t)(S_TILE * sizeof(float));

    const int ntiles = K / KT_;

    {
#pragma unroll
        for (int c = 0; c < 4; c++)
            cp_async16(bs_sm + (uint32_t)(c * 32 * sizeof(float)), Bp + bc0 + c * 32);
        cp_commit();
        float4 av[4];
#pragma unroll
        for (int c = 0; c < 4; c++) av[c] = *(const float4*)(Ap + c * 4);
        float* as0 = AsBase;
#pragma unroll
        for (int c = 0; c < 4; c++) {
            as0[(akh + c * 4 + 0) * S_STRIDE + am] = av[c].x;
            as0[(akh + c * 4 + 1) * S_STRIDE + am] = av[c].y;
            as0[(akh + c * 4 + 2) * S_STRIDE + am] = av[c].z;
            as0[(akh + c * 4 + 3) * S_STRIDE + am] = av[c].w;
        }
        cp_wait0();
    }
    __syncthreads();

    for (int kt = 0; kt < ntiles; kt++) {
        const int cur = kt & 1;
        const int nxt = cur ^ 1;
        const bool more = (kt + 1) < ntiles;
        float4 av[4];
        if (more) {
            const float* bsrc = Bp + (size_t)(kt + 1) * KT_ * Nn;
#pragma unroll
            for (int c = 0; c < 4; c++)
                cp_async16(bs_sm + (uint32_t)nxt * stage_b + (uint32_t)(c * 32 * sizeof(float)),
                           bsrc + bc0 + c * 32);
            cp_commit();
            const float* asrc = Ap + (kt + 1) * KT_;
#pragma unroll
            for (int c = 0; c < 4; c++) av[c] = *(const float4*)(asrc + c * 4);
        }

        const float* Asc = AsBase + (size_t)cur * S_TILE;
        const float* Bsc = BsBase + (size_t)cur * S_TILE;
#pragma unroll
        for (int k = 0; k < KT_; k++) {
            const float* as = Asc + (size_t)k * S_STRIDE + ty * 8;
            float4 af0 = *(const float4*)(as);
            float4 af1 = *(const float4*)(as + 4);
            const float* bs = Bsc + (size_t)k * S_STRIDE + tx * 8;
            ulonglong2 bv0 = *(const ulonglong2*)(bs);
            ulonglong2 bv1 = *(const ulonglong2*)(bs + 4);
            u64 bb[4] = {bv0.x, bv0.y, bv1.x, bv1.y};
            u64 aa[8] = {dup2(af0.x), dup2(af0.y), dup2(af0.z), dup2(af0.w),
                         dup2(af1.x), dup2(af1.y), dup2(af1.z), dup2(af1.w)};
#pragma unroll
            for (int i = 0; i < 8; i++)
#pragma unroll
                for (int j = 0; j < 4; j++)
                    acc[i][j] = fma2(aa[i], bb[j], acc[i][j]);
        }

        if (more) {
            float* asn = AsBase + (size_t)nxt * S_TILE;
#pragma unroll
            for (int c = 0; c < 4; c++) {
                asn[(akh + c * 4 + 0) * S_STRIDE + am] = av[c].x;
                asn[(akh + c * 4 + 1) * S_STRIDE + am] = av[c].y;
                asn[(akh + c * 4 + 2) * S_STRIDE + am] = av[c].z;
                asn[(akh + c * 4 + 3) * S_STRIDE + am] = av[c].w;
            }
            cp_wait0();
        }
        __syncthreads();
    }

#pragma unroll
    for (int i = 0; i < 8; i++) {
        const int row = bm + ty * 8 + i;
        float m1 = 0.0f, m2 = 0.0f;
        if (EPI == 1) m1 = mask1[row];
        if (EPI == 3) { m1 = mask1[row]; m2 = mask2[row]; }
        float vals[8];
#pragma unroll
        for (int j = 0; j < 4; j++) {
            float2 f = upk(acc[i][j]);
            vals[2 * j]     = f.x;
            vals[2 * j + 1] = f.y;
        }
        float out8[8];
#pragma unroll
        for (int jj = 0; jj < 8; jj++) {
            const int col = bn + tx * 8 + jj;
            float c = vals[jj] + bias[col];
            if (EPI == 0) {
                c = tanhf(c);
            } else if (EPI == 1) {
                if (col >= 64) c = -softplusf(c);
                c *= m1;
            } else if (EPI == 3) {
                if (col >= 64) c = -softplusf(c);
                c *= m1;
                c = m2 * (aux[(size_t)row * 128 + col] + c);
            }
            out8[jj] = c;
        }
        float4* cp = (float4*)(C + (size_t)row * Nn + bn + tx * 8);
        cp[0] = make_float4(out8[0], out8[1], out8[2], out8[3]);
        cp[1] = make_float4(out8[4], out8[5], out8[6], out8[7]);
    }
}

// ---------------- GRU (R4 form): 3 phases, Ug column-resident, f32x2 dots ----------------
__global__ void __launch_bounds__(384, 1) gru_kernel(const float* __restrict__ Ug) {
    const int n = blockIdx.x;
    const int j = threadIdx.x;  // 0..383
    __shared__ __align__(16) float h[128];
    __shared__ float rbuf[128], zbuf[128], nbuf[128];
    u64 ug2[64];
#pragma unroll
    for (int k2 = 0; k2 < 64; k2++)
        ug2[k2] = pk2(Ug[(2 * k2) * 384 + j], Ug[(2 * k2 + 1) * 384 + j]);
    if (j < 128) h[j] = 0.0f;

    const float* gbase = g_gall + (size_t)n * T_ * 384;
    float gv = gbase[j];  // prefetch t=0
    __syncthreads();
    for (int t = 0; t < T_; t++) {
        float gvn = 0.0f;
        if (t + 1 < T_) gvn = gbase[(size_t)(t + 1) * 384 + j];

        u64 s4[4] = {0ULL, 0ULL, 0ULL, 0ULL};
#pragma unroll
        for (int k = 0; k < 128; k += 8) {
            ulonglong2 h0 = *(const ulonglong2*)&h[k];
            ulonglong2 h1 = *(const ulonglong2*)&h[k + 4];
            s4[0] = fma2(h0.x, ug2[k / 2],     s4[0]);
            s4[1] = fma2(h0.y, ug2[k / 2 + 1], s4[1]);
            s4[2] = fma2(h1.x, ug2[k / 2 + 2], s4[2]);
            s4[3] = fma2(h1.y, ug2[k / 2 + 3], s4[3]);
        }
        float2 f0 = upk(s4[0]), f1 = upk(s4[1]), f2 = upk(s4[2]), f3 = upk(s4[3]);
        float s = ((f0.x + f0.y) + (f1.x + f1.y)) + ((f2.x + f2.y) + (f3.x + f3.y));
        if (j < 256) {
            float val = 1.0f / (1.0f + expf(-(gv + s)));
            if (j < 128) rbuf[j] = val; else zbuf[j - 128] = val;
        }
        __syncthreads();
        if (j >= 256) {
            nbuf[j - 256] = tanhf(gv + rbuf[j - 256] * s);
        }
        __syncthreads();
        if (j < 128) {
            float z = zbuf[j];
            float hn = (1.0f - z) * nbuf[j] + z * h[j];
            h[j] = hn;
            g_hs[(size_t)(n * T_ + t) * 128 + j] = hn;
        }
        gv = gvn;
        __syncthreads();
    }
}

// ---------------- filter (R4 form): 256 threads, prefetched inputs, f32x2 dots ----------------
__global__ void __launch_bounds__(256, 1) filter_kernel(
    const float* __restrict__ u, const float* __restrict__ Wd1,
    const float* __restrict__ bd1, const float* __restrict__ Wd2,
    const float* __restrict__ bd2, const float* __restrict__ logQ,
    float* __restrict__ out)
{
    const int n = blockIdx.x;
    const int tid = threadIdx.x;          // 0..255
    const int q = tid >> 6, j = tid & 63;
    __shared__ __align__(16) float xbuf[72];
    __shared__ __align__(16) float hdyn[256];
    __shared__ float part[4][64];
    __shared__ float vshr[64];
    __shared__ float noi[64];

    u64 wc2[36];
#pragma unroll
    for (int m = 0; m < 36; m++)
        wc2[m] = pk2(Wd1[(2 * m) * 256 + tid], Wd1[(2 * m + 1) * 256 + tid]);
    u64 w2[32];
#pragma unroll
    for (int m = 0; m < 32; m++)
        w2[m] = pk2(Wd2[(q * 64 + 2 * m) * 64 + j], Wd2[(q * 64 + 2 * m + 1) * 64 + j]);
    const float bd1v = bd1[tid];
    const float bd2j = bd2[j];
    const float Qj = softplusf(logQ[j]);

    if (tid < 64) { xbuf[tid] = 0.0f; vshr[tid] = 1.0f; }

    float* outZ = out;
    float* outS = out + (size_t)NT_ * 64;
    float* outP = out + (size_t)NT_ * 192;

    const size_t base = (size_t)n * T_;
    float a1c = 0.0f, a2c = 0.0f, uc = 0.0f;
    unsigned int s0c = 0u, s1c = 0u;
    if (tid < 64) {
        a1c = g_ab[(base + 0) * 128 + j];
        a2c = g_ab[(base + 0) * 128 + 64 + j];
        s0c = g_skeys[(base + 0) * 2];
        s1c = g_skeys[(base + 0) * 2 + 1];
    } else if (tid < 72) {
        uc = u[(base + 0) * 8 + (tid - 64)];
    }
    __syncthreads();

    for (int t = 0; t < T_; t++) {
        const size_t row = base + t;
        if (tid < 64) {
            uint2 r = tf2x32(s0c, s1c, 0u, (unsigned int)j);
            float f = bits_to_unit(r.x ^ r.y);
            float uu = __fadd_rn(__fmul_rn(f, 2.0f), -0.99999994f);
            uu = fmaxf(uu, -0.99999994f);
            noi[j] = 1.41421356f * erfinvf(uu);
        } else if (tid < 72) {
            xbuf[tid] = uc;
        }
        __syncthreads();

        float a1n = 0.0f, a2n = 0.0f, un = 0.0f;
        unsigned int s0n = 0u, s1n = 0u;
        if (t + 1 < T_) {
            if (tid < 64) {
                a1n = g_ab[(row + 1) * 128 + j];
                a2n = g_ab[(row + 1) * 128 + 64 + j];
                s0n = g_skeys[(row + 1) * 2];
                s1n = g_skeys[(row + 1) * 2 + 1];
            } else if (tid < 72) {
                un = u[(row + 1) * 8 + (tid - 64)];
            }
        }

        u64 s2a = pk2(bd1v, 0.0f), s2b = 0ULL;
#pragma unroll
        for (int k = 0; k < 72; k += 4) {
            ulonglong2 xv = *(const ulonglong2*)&xbuf[k];
            s2a = fma2(xv.x, wc2[k / 2],     s2a);
            s2b = fma2(xv.y, wc2[k / 2 + 1], s2b);
        }
        {
            float2 fa = upk(s2a), fb = upk(s2b);
            hdyn[tid] = tanhf((fa.x + fa.y) + (fb.x + fb.y));
        }
        __syncthreads();

        u64 p2a = 0ULL, p2b = 0ULL;
#pragma unroll
        for (int k = 0; k < 64; k += 4) {
            ulonglong2 hv = *(const ulonglong2*)&hdyn[q * 64 + k];
            p2a = fma2(hv.x, w2[k / 2],     p2a);
            p2b = fma2(hv.y, w2[k / 2 + 1], p2b);
        }
        {
            float2 fa = upk(p2a), fb = upk(p2b);
            part[q][j] = (fa.x + fa.y) + (fb.x + fb.y);
        }
        __syncthreads();

        if (tid < 64) {
            float mp = ((part[0][j] + part[1][j]) + (part[2][j] + part[3][j])) + bd2j;
            float vp = vshr[j] + Qj;
            float Jp = 1.0f / vp;
            float hp = mp * Jp;
            float Jpost = Jp - 2.0f * a2c;
            float vn = 1.0f / Jpost;
            float mn = (hp + a1c) * vn;
            float zz = mn + sqrtf(vn) * noi[j];
            xbuf[j] = mn;
            vshr[j] = vn;
            outZ[row * 64 + j] = zz;
            outS[row * 128 + j] = mn;
            outS[row * 128 + 64 + j] = vn;
            outP[row * 128 + j] = mp;
            outP[row * 128 + 64 + j] = vp;
        }
        a1c = a1n; a2c = a2n; s0c = s0n; s1c = s1n; uc = un;
        __syncthreads();
    }
}

// ---------------- host launcher ----------------
extern "C" void kernel_launch(void* const* d_in, const int* in_sizes, int n_in,
                              void* d_out, int out_size) {
    (void)in_sizes; (void)n_in; (void)out_size;
    const int*   seed    = (const int*)d_in[3];
    const float* dropout = (const float*)d_in[4];
    const float* y   = (const float*)d_in[1];
    const float* u   = (const float*)d_in[2];
    const float* W1  = (const float*)d_in[5];
    const float* b1  = (const float*)d_in[6];
    const float* W2  = (const float*)d_in[7];
    const float* b2  = (const float*)d_in[8];
    const float* Wg  = (const float*)d_in[9];
    const float* Ug  = (const float*)d_in[10];
    const float* bg  = (const float*)d_in[11];
    const float* Wo  = (const float*)d_in[12];
    const float* bo  = (const float*)d_in[13];
    const float* Wd1 = (const float*)d_in[14];
    const float* bd1 = (const float*)d_in[15];
    const float* Wd2 = (const float*)d_in[16];
    const float* bd2 = (const float*)d_in[17];
    const float* logQ= (const float*)d_in[18];
    float* out = (float*)d_out;

    float *ph, *pa, *pg, *phs, *pab, *pmA, *pmB, *pmAB;
    cudaGetSymbolAddress((void**)&ph,   g_h);
    cudaGetSymbolAddress((void**)&pa,   g_a);
    cudaGetSymbolAddress((void**)&pg,   g_gall);
    cudaGetSymbolAddress((void**)&phs,  g_hs);
    cudaGetSymbolAddress((void**)&pab,  g_ab);
    cudaGetSymbolAddress((void**)&pmA,  g_maskA);
    cudaGetSymbolAddress((void**)&pmB,  g_maskB);
    cudaGetSymbolAddress((void**)&pmAB, g_maskAB);

    const int smem_bytes = SMEM_FLOATS * (int)sizeof(float);

    static cudaStream_t s_chain = nullptr;
    static cudaEvent_t ev_fork = nullptr, ev_join = nullptr;
    if (s_chain == nullptr) {
        cudaStreamCreateWithFlags(&s_chain, cudaStreamNonBlocking);
        cudaEventCreateWithFlags(&ev_fork, cudaEventDisableTiming);
        cudaEventCreateWithFlags(&ev_join, cudaEventDisableTiming);
        cudaFuncSetAttribute(sgemm_k<0>, cudaFuncAttributeMaxDynamicSharedMemorySize, smem_bytes);
        cudaFuncSetAttribute(sgemm_k<1>, cudaFuncAttributeMaxDynamicSharedMemorySize, smem_bytes);
        cudaFuncSetAttribute(sgemm_k<2>, cudaFuncAttributeMaxDynamicSharedMemorySize, smem_bytes);
        cudaFuncSetAttribute(sgemm_k<3>, cudaFuncAttributeMaxDynamicSharedMemorySize, smem_bytes);
    }

    key_kernel<<<1, 1>>>(seed, dropout);

    // fork: serial Threefry chain overlaps the GEMM pipeline
    cudaEventRecord(ev_fork, 0);
    cudaStreamWaitEvent(s_chain, ev_fork, 0);
    chain_kernel<<<1, 128, 0, s_chain>>>();
    cudaEventRecord(ev_join, s_chain);

    mask_kernel<<<(NT_ + 255) / 256, 256>>>();

    // h = tanh(y @ W1 + b1)
    sgemm_k<0><<<dim3(HE_ / 128, NT_ / 128), 256, smem_bytes>>>(y, W1, b1, ph, NT_, HE_, DO_,
                                                                nullptr, nullptr, nullptr);
    // a = constrain(h @ W2 + b2) * maskA
    sgemm_k<1><<<dim3(DN_ / 128, NT_ / 128), 256, smem_bytes>>>(ph, W2, b2, pa, NT_, DN_, HE_,
                                                                pmA, nullptr, nullptr);
    // g_all = a @ Wg + bg
    sgemm_k<2><<<dim3(3 * HG_ / 128, NT_ / 128), 256, smem_bytes>>>(pa, Wg, bg, pg, NT_, 3 * HG_, DN_,
                                                                    nullptr, nullptr, nullptr);
    // GRU scan
    gru_kernel<<<N_, 384>>>(Ug);
    // ab = maskAB * (a + constrain(hs @ Wo + bo) * maskB)
    sgemm_k<3><<<dim3(DN_ / 128, NT_ / 128), 256, smem_bytes>>>(phs, Wo, bo, pab, NT_, DN_, HG_,
                                                                pmB, pmAB, pa);

    // join: filter needs the sample subkeys
    cudaStreamWaitEvent(0, ev_join, 0);
    // filter + sampling
    filter_kernel<<<N_, 256>>>(u, Wd1, bd1, Wd2, bd2, logQ, out);
}